// round 6
// baseline (speedup 1.0000x reference)
#include <cuda_runtime.h>
#include <math.h>

#define NN   50000
#define EE   800000
#define DD   64
#define KK   3
#define AGG_EPS 1e-6f
#define BN_EPS  1e-5f

// ---------------- scratch (static device globals; no dynamic alloc allowed) ----------
__device__ float g_Ax[NN * DD];          // x @ Wa + ba
__device__ float g_Dx[NN * DD];          // x @ Wd + bd
__device__ float g_Bx[KK * NN * DD];     // per-hop states @ Wb[k] + bb[k]
__device__ int   g_cnt[NN];              // per-destination edge counts
__device__ int   g_off[NN + 1];          // CSR offsets
__device__ int   g_cur[NN];              // scatter cursors
__device__ int   g_srcpk[EE];            // packed (src | k<<28) sorted by destination
__device__ float g_sum[DD];              // BN per-channel sum
__device__ float g_sumsq[DD];            // BN per-channel sum of squares

// ---------------- kernel 0: zero the accumulated scratch (graph replays!) ------------
__global__ void k_zero() {
    int idx = blockIdx.x * blockDim.x + threadIdx.x;
    if (idx < NN) g_cnt[idx] = 0;
    if (idx < DD) { g_sum[idx] = 0.f; g_sumsq[idx] = 0.f; }
}

// ---------------- kernel 1: 5 fused GEMMs  [N,64] @ [64,64] + bias -------------------
// blockIdx.y selects which GEMM: 0=Ax, 1=Dx, 2..4 = Bx[k] (states idx 2,1,0)
// Thread layout: 256 threads = 4 row-groups x 64 output columns.
// W column lives in registers (coalesced load), x rows broadcast from smem.
__global__ void __launch_bounds__(256) k_gemm5(
    const float* __restrict__ xs,
    const float* __restrict__ Wa, const float* __restrict__ ba,
    const float* __restrict__ Wd, const float* __restrict__ bd,
    const float* __restrict__ Wb, const float* __restrict__ bb)
{
    const int which = blockIdx.y;
    const float* X; const float* W; const float* bias; float* out;
    switch (which) {
        case 0: X = xs + 2 * NN * DD; W = Wa;               bias = ba;          out = g_Ax;              break;
        case 1: X = xs + 2 * NN * DD; W = Wd;               bias = bd;          out = g_Dx;              break;
        case 2: X = xs + 2 * NN * DD; W = Wb;               bias = bb;          out = g_Bx;              break;
        case 3: X = xs + 1 * NN * DD; W = Wb + 1 * DD * DD; bias = bb + 1 * DD; out = g_Bx + 1 * NN * DD; break;
        default:X = xs;               W = Wb + 2 * DD * DD; bias = bb + 2 * DD; out = g_Bx + 2 * NN * DD; break;
    }

    const int tid = threadIdx.x;
    const int o   = tid & 63;        // output column
    const int rq  = tid >> 6;        // row group 0..3

    // W column o into registers (coalesced across o)
    float w[DD];
#pragma unroll
    for (int k = 0; k < DD; ++k) w[k] = __ldg(&W[k * DD + o]);
    const float bo = __ldg(&bias[o]);

    __shared__ float xsm[64 * DD];   // 64 rows x 64 cols = 16 KB
    const int row0 = blockIdx.x * 64;
    const int nrows = (NN - row0) < 64 ? (NN - row0) : 64;

    // cooperative coalesced load of the x tile
    const float4* X4 = reinterpret_cast<const float4*>(X + (size_t)row0 * DD);
    float4* xsm4 = reinterpret_cast<float4*>(xsm);
    for (int idx = tid; idx < nrows * (DD / 4); idx += 256) xsm4[idx] = __ldg(&X4[idx]);
    __syncthreads();

    for (int r = rq; r < nrows; r += 4) {
        const float* xr = xsm + r * DD;
        float a0 = 0.f, a1 = 0.f, a2 = 0.f, a3 = 0.f;
#pragma unroll
        for (int k = 0; k < DD; k += 4) {
            a0 = fmaf(xr[k + 0], w[k + 0], a0);
            a1 = fmaf(xr[k + 1], w[k + 1], a1);
            a2 = fmaf(xr[k + 2], w[k + 2], a2);
            a3 = fmaf(xr[k + 3], w[k + 3], a3);
        }
        out[(size_t)(row0 + r) * DD + o] = (a0 + a1) + (a2 + a3) + bo;
    }
}

// ---------------- kernel 2: histogram of destinations --------------------------------
__global__ void k_hist(const int* __restrict__ dst) {
    int e = blockIdx.x * blockDim.x + threadIdx.x;
    if (e < EE) atomicAdd(&g_cnt[dst[e]], 1);
}

// ---------------- kernel 3: single-block exclusive scan over 50k counts --------------
__global__ void __launch_bounds__(1024) k_scan() {
    const int t = threadIdx.x;
    const int CH = (NN + 1023) / 1024;       // 49
    const int lo = t * CH;
    const int hi = min(lo + CH, NN);

    int local = 0;
    for (int i = lo; i < hi; ++i) local += g_cnt[i];

    __shared__ int sm[1024];
    sm[t] = local;
    __syncthreads();
#pragma unroll
    for (int ofs = 1; ofs < 1024; ofs <<= 1) {
        int v = (t >= ofs) ? sm[t - ofs] : 0;
        __syncthreads();
        sm[t] += v;
        __syncthreads();
    }
    int excl = sm[t] - local;
    if (t == 1023) g_off[NN] = sm[1023];

    int run = excl;
    for (int i = lo; i < hi; ++i) {
        g_off[i] = run;
        g_cur[i] = run;
        run += g_cnt[i];
    }
}

// ---------------- kernel 4: scatter edges into destination-sorted order --------------
__global__ void k_scatter(const int* __restrict__ src, const int* __restrict__ dst,
                          const int* __restrict__ attr) {
    int e = blockIdx.x * blockDim.x + threadIdx.x;
    if (e >= EE) return;
    int i  = dst[e];
    int j  = src[e];
    int ke = attr[e] - 1;                    // 0..2
    int pos = atomicAdd(&g_cur[i], 1);
    g_srcpk[pos] = j | (ke << 28);
}

// ---------------- kernel 5: per-node gated aggregation (atomic-free) -----------------
// one 64-thread block per node, thread d = channel d; num/den per hop in registers.
__global__ void __launch_bounds__(64) k_aggregate(float* __restrict__ out) {
    const int i = blockIdx.x;
    const int d = threadIdx.x;

    const float dx = g_Dx[(size_t)i * DD + d];
    float n0 = 0.f, n1 = 0.f, n2 = 0.f;
    float d0 = 0.f, d1 = 0.f, d2 = 0.f;

    const int s = g_off[i], e = g_off[i + 1];
    for (int p = s; p < e; ++p) {
        int pk = __ldg(&g_srcpk[p]);                  // uniform across block
        int j  = pk & 0x0FFFFFFF;
        int ke = pk >> 28;
        float bx = __ldg(&g_Bx[((size_t)ke * NN + j) * DD + d]);
        float sg = 1.f / (1.f + __expf(-(dx + bx)));
        if (ke == 0)       { n0 = fmaf(sg, bx, n0); d0 += sg; }
        else if (ke == 1)  { n1 = fmaf(sg, bx, n1); d1 += sg; }
        else               { n2 = fmaf(sg, bx, n2); d2 += sg; }
    }
    float eta = n0 / (d0 + AGG_EPS) + n1 / (d1 + AGG_EPS) + n2 / (d2 + AGG_EPS);
    out[(size_t)i * DD + d] = g_Ax[(size_t)i * DD + d] + (1.0f / 3.0f) * eta;
}

// ---------------- kernel 6: BN batch statistics ---------------------------------------
__global__ void __launch_bounds__(256) k_stats(const float* __restrict__ x) {
    const int tid = threadIdx.x;
    const int d  = tid & 63;
    const int rq = tid >> 6;
    float s = 0.f, q = 0.f;
    for (int r = blockIdx.x * 4 + rq; r < NN; r += gridDim.x * 4) {
        float v = x[(size_t)r * DD + d];
        s += v;
        q = fmaf(v, v, q);
    }
    __shared__ float ss[256], sq[256];
    ss[tid] = s; sq[tid] = q;
    __syncthreads();
    if (rq == 0) {
        s = ss[d] + ss[d + 64] + ss[d + 128] + ss[d + 192];
        q = sq[d] + sq[d + 64] + sq[d + 128] + sq[d + 192];
        atomicAdd(&g_sum[d], s);
        atomicAdd(&g_sumsq[d], q);
    }
}

// ---------------- kernel 7: normalize + affine + relu (in place) ---------------------
__global__ void k_norm(float* __restrict__ x,
                       const float* __restrict__ gamma, const float* __restrict__ beta) {
    int idx = blockIdx.x * blockDim.x + threadIdx.x;
    if (idx >= NN * DD) return;
    int d = idx & 63;
    const float invN = 1.0f / (float)NN;
    float mean = g_sum[d] * invN;
    float var  = g_sumsq[d] * invN - mean * mean;
    var = fmaxf(var, 0.f);
    float inv = rsqrtf(var + BN_EPS);
    float v = x[idx];
    float y = gamma[d] * (v - mean) * inv + beta[d];
    x[idx] = fmaxf(y, 0.f);
}

// =====================================================================================
extern "C" void kernel_launch(void* const* d_in, const int* in_sizes, int n_in,
                              void* d_out, int out_size) {
    const float* xs    = (const float*)d_in[0];   // [3, N, 64]
    const int*   eidx  = (const int*)  d_in[1];   // [2, E]: row0 = src j, row1 = dst i
    const int*   eattr = (const int*)  d_in[2];   // [E], 1..3
    const float* Wa    = (const float*)d_in[3];
    const float* ba    = (const float*)d_in[4];
    const float* Wd    = (const float*)d_in[5];
    const float* bd    = (const float*)d_in[6];
    const float* Wb    = (const float*)d_in[7];   // [3,64,64]
    const float* bb    = (const float*)d_in[8];   // [3,64]
    const float* gamma = (const float*)d_in[9];
    const float* beta  = (const float*)d_in[10];
    float* out = (float*)d_out;

    const int* src = eidx;
    const int* dst = eidx + EE;

    // 0) zero accumulated scratch
    k_zero<<<(NN + 255) / 256, 256>>>();

    // 1) five GEMMs
    dim3 ggrid((NN + 63) / 64, 5);
    k_gemm5<<<ggrid, 256>>>(xs, Wa, ba, Wd, bd, Wb, bb);

    // 2-4) CSR build by destination
    k_hist<<<(EE + 255) / 256, 256>>>(dst);
    k_scan<<<1, 1024>>>();
    k_scatter<<<(EE + 255) / 256, 256>>>(src, dst, eattr);

    // 5) gated aggregation -> x_new into d_out
    k_aggregate<<<NN, 64>>>(out);

    // 6-7) batchnorm (training-mode batch stats) + relu, in place
    k_stats<<<128, 256>>>(out);
    k_norm<<<(NN * DD + 255) / 256, 256>>>(out, gamma, beta);
}

// round 8
// speedup vs baseline: 1.5165x; 1.5165x over previous
#include <cuda_runtime.h>
#include <math.h>

#define NN   50000
#define EE   800000
#define DD   64
#define KK   3
#define AGG_EPS 1e-6f
#define BN_EPS  1e-5f

#define SCAN_NB 98          // 98 blocks * 512 = 50176 >= NN

// ---------------- scratch (static device globals; no dynamic alloc allowed) ----------
__device__ float g_Ax[NN * DD];          // x @ Wa + ba
__device__ float g_Dx[NN * DD];          // x @ Wd + bd
__device__ float g_Bx[KK * NN * DD];     // per-hop states @ Wb[k] + bb[k]
__device__ int   g_cnt[NN];              // per-destination edge counts
__device__ int   g_off[NN + 1];          // CSR offsets
__device__ int   g_cur[NN];              // scatter cursors
__device__ int   g_srcpk[EE];            // packed (src | k<<28) sorted by destination
__device__ int   g_bsum[SCAN_NB];        // per-block sums for the scan
__device__ int   g_boff[SCAN_NB];        // scanned block offsets
__device__ float g_sum[DD];              // BN per-channel sum
__device__ float g_sumsq[DD];            // BN per-channel sum of squares

// ---------------- kernel 0: zero the accumulated scratch (graph replays!) ------------
__global__ void k_zero() {
    int idx = blockIdx.x * blockDim.x + threadIdx.x;
    if (idx < NN) g_cnt[idx] = 0;
    if (idx < DD) { g_sum[idx] = 0.f; g_sumsq[idx] = 0.f; }
}

// ---------------- kernel 1: 5 fused GEMMs  [N,64] @ [64,64] + bias -------------------
__global__ void __launch_bounds__(256) k_gemm5(
    const float* __restrict__ xs,
    const float* __restrict__ Wa, const float* __restrict__ ba,
    const float* __restrict__ Wd, const float* __restrict__ bd,
    const float* __restrict__ Wb, const float* __restrict__ bb)
{
    const int which = blockIdx.y;
    const float* X; const float* W; const float* bias; float* out;
    switch (which) {
        case 0: X = xs + 2 * NN * DD; W = Wa;               bias = ba;          out = g_Ax;              break;
        case 1: X = xs + 2 * NN * DD; W = Wd;               bias = bd;          out = g_Dx;              break;
        case 2: X = xs + 2 * NN * DD; W = Wb;               bias = bb;          out = g_Bx;              break;
        case 3: X = xs + 1 * NN * DD; W = Wb + 1 * DD * DD; bias = bb + 1 * DD; out = g_Bx + 1 * NN * DD; break;
        default:X = xs;               W = Wb + 2 * DD * DD; bias = bb + 2 * DD; out = g_Bx + 2 * NN * DD; break;
    }

    const int tid = threadIdx.x;
    const int o   = tid & 63;        // output column
    const int rq  = tid >> 6;        // row group 0..3

    float w[DD];
#pragma unroll
    for (int k = 0; k < DD; ++k) w[k] = __ldg(&W[k * DD + o]);
    const float bo = __ldg(&bias[o]);

    __shared__ float xsm[64 * DD];   // 16 KB
    const int row0 = blockIdx.x * 64;
    const int nrows = (NN - row0) < 64 ? (NN - row0) : 64;

    const float4* X4 = reinterpret_cast<const float4*>(X + (size_t)row0 * DD);
    float4* xsm4 = reinterpret_cast<float4*>(xsm);
    for (int idx = tid; idx < nrows * (DD / 4); idx += 256) xsm4[idx] = __ldg(&X4[idx]);
    __syncthreads();

    for (int r = rq; r < nrows; r += 4) {
        const float* xr = xsm + r * DD;
        float a0 = 0.f, a1 = 0.f, a2 = 0.f, a3 = 0.f;
#pragma unroll
        for (int k = 0; k < DD; k += 4) {
            a0 = fmaf(xr[k + 0], w[k + 0], a0);
            a1 = fmaf(xr[k + 1], w[k + 1], a1);
            a2 = fmaf(xr[k + 2], w[k + 2], a2);
            a3 = fmaf(xr[k + 3], w[k + 3], a3);
        }
        out[(size_t)(row0 + r) * DD + o] = (a0 + a1) + (a2 + a3) + bo;
    }
}

// ---------------- kernel 2: histogram of destinations --------------------------------
__global__ void k_hist(const int* __restrict__ dst) {
    int e = blockIdx.x * blockDim.x + threadIdx.x;
    if (e < EE) atomicAdd(&g_cnt[dst[e]], 1);
}

// ---------------- kernels 3a/3b/3c: multi-block exclusive scan of g_cnt --------------
// 3a: per-block sums (98 blocks x 512 threads, 512 counts each)
__global__ void __launch_bounds__(512) k_scan_sums() {
    const int t = threadIdx.x;
    const int idx = blockIdx.x * 512 + t;
    int v = (idx < NN) ? g_cnt[idx] : 0;

    __shared__ int sm[512];
    sm[t] = v;
    __syncthreads();
    // tree reduce
#pragma unroll
    for (int ofs = 256; ofs > 0; ofs >>= 1) {
        if (t < ofs) sm[t] += sm[t + ofs];
        __syncthreads();
    }
    if (t == 0) g_bsum[blockIdx.x] = sm[0];
}

// 3b: scan the 98 block sums (1 tiny block)
__global__ void __launch_bounds__(128) k_scan_tops() {
    const int t = threadIdx.x;
    int v = (t < SCAN_NB) ? g_bsum[t] : 0;
    __shared__ int sm[128];
    sm[t] = v;
    __syncthreads();
#pragma unroll
    for (int ofs = 1; ofs < 128; ofs <<= 1) {
        int u = (t >= ofs) ? sm[t - ofs] : 0;
        __syncthreads();
        sm[t] += u;
        __syncthreads();
    }
    if (t < SCAN_NB) g_boff[t] = sm[t] - v;   // exclusive
    if (t == 0) g_off[NN] = EE;               // total is a known constant
}

// 3c: local exclusive scan + block offset -> g_off / g_cur
__global__ void __launch_bounds__(512) k_scan_final() {
    const int t = threadIdx.x;
    const int idx = blockIdx.x * 512 + t;
    int v = (idx < NN) ? g_cnt[idx] : 0;

    __shared__ int sm[512];
    sm[t] = v;
    __syncthreads();
#pragma unroll
    for (int ofs = 1; ofs < 512; ofs <<= 1) {
        int u = (t >= ofs) ? sm[t - ofs] : 0;
        __syncthreads();
        sm[t] += u;
        __syncthreads();
    }
    if (idx < NN) {
        int excl = sm[t] - v + g_boff[blockIdx.x];
        g_off[idx] = excl;
        g_cur[idx] = excl;
    }
}

// ---------------- kernel 4: scatter edges into destination-sorted order --------------
__global__ void k_scatter(const int* __restrict__ src, const int* __restrict__ dst,
                          const int* __restrict__ attr) {
    int e = blockIdx.x * blockDim.x + threadIdx.x;
    if (e >= EE) return;
    int i  = dst[e];
    int j  = src[e];
    int ke = attr[e] - 1;                    // 0..2
    int pos = atomicAdd(&g_cur[i], 1);
    g_srcpk[pos] = j | (ke << 28);
}

// ---------------- kernel 5: per-node gated aggregation (atomic-free) -----------------
// one 64-thread block per node; edge list staged via smem, unroll x4 for MLP.
__global__ void __launch_bounds__(64) k_aggregate(float* __restrict__ out) {
    const int i = blockIdx.x;
    const int d = threadIdx.x;

    __shared__ int pksm[64];

    const float dx = g_Dx[i * DD + d];
    float n0 = 0.f, n1 = 0.f, n2 = 0.f;
    float d0 = 0.f, d1 = 0.f, d2 = 0.f;

    const int s = g_off[i], e = g_off[i + 1];

#define PROC(PK, BX) {                                                        \
        int _ke = (PK) >> 28;                                                 \
        float _sg = __fdividef(1.f, 1.f + __expf(-(dx + (BX))));              \
        float _nb = _sg * (BX);                                               \
        if (_ke == 0)      { n0 += _nb; d0 += _sg; }                          \
        else if (_ke == 1) { n1 += _nb; d1 += _sg; }                          \
        else               { n2 += _nb; d2 += _sg; } }

    for (int base = s; base < e; base += 64) {
        int m = e - base; if (m > 64) m = 64;
        if (d < m) pksm[d] = __ldg(&g_srcpk[base + d]);
        __syncthreads();
        int p = 0;
        for (; p + 4 <= m; p += 4) {
            int pk0 = pksm[p + 0], pk1 = pksm[p + 1];
            int pk2 = pksm[p + 2], pk3 = pksm[p + 3];
            float bx0 = __ldg(&g_Bx[(((pk0 >> 28) * NN + (pk0 & 0x0FFFFFFF)) << 6) + d]);
            float bx1 = __ldg(&g_Bx[(((pk1 >> 28) * NN + (pk1 & 0x0FFFFFFF)) << 6) + d]);
            float bx2 = __ldg(&g_Bx[(((pk2 >> 28) * NN + (pk2 & 0x0FFFFFFF)) << 6) + d]);
            float bx3 = __ldg(&g_Bx[(((pk3 >> 28) * NN + (pk3 & 0x0FFFFFFF)) << 6) + d]);
            PROC(pk0, bx0); PROC(pk1, bx1); PROC(pk2, bx2); PROC(pk3, bx3);
        }
        for (; p < m; ++p) {
            int pk = pksm[p];
            float bx = __ldg(&g_Bx[(((pk >> 28) * NN + (pk & 0x0FFFFFFF)) << 6) + d]);
            PROC(pk, bx);
        }
        __syncthreads();
    }
#undef PROC

    float eta = n0 / (d0 + AGG_EPS) + n1 / (d1 + AGG_EPS) + n2 / (d2 + AGG_EPS);
    out[i * DD + d] = g_Ax[i * DD + d] + (1.0f / 3.0f) * eta;
}

// ---------------- kernel 6: BN batch statistics ---------------------------------------
__global__ void __launch_bounds__(256) k_stats(const float* __restrict__ x) {
    const int tid = threadIdx.x;
    const int d  = tid & 63;
    const int rq = tid >> 6;
    float s = 0.f, q = 0.f;
    for (int r = blockIdx.x * 4 + rq; r < NN; r += gridDim.x * 4) {
        float v = x[(size_t)r * DD + d];
        s += v;
        q = fmaf(v, v, q);
    }
    __shared__ float ss[256], sq[256];
    ss[tid] = s; sq[tid] = q;
    __syncthreads();
    if (rq == 0) {
        s = ss[d] + ss[d + 64] + ss[d + 128] + ss[d + 192];
        q = sq[d] + sq[d + 64] + sq[d + 128] + sq[d + 192];
        atomicAdd(&g_sum[d], s);
        atomicAdd(&g_sumsq[d], q);
    }
}

// ---------------- kernel 7: normalize + affine + relu (in place) ---------------------
__global__ void k_norm(float* __restrict__ x,
                       const float* __restrict__ gamma, const float* __restrict__ beta) {
    int idx = blockIdx.x * blockDim.x + threadIdx.x;
    if (idx >= NN * DD) return;
    int d = idx & 63;
    const float invN = 1.0f / (float)NN;
    float mean = g_sum[d] * invN;
    float var  = g_sumsq[d] * invN - mean * mean;
    var = fmaxf(var, 0.f);
    float inv = rsqrtf(var + BN_EPS);
    float v = x[idx];
    float y = gamma[d] * (v - mean) * inv + beta[d];
    x[idx] = fmaxf(y, 0.f);
}

// =====================================================================================
extern "C" void kernel_launch(void* const* d_in, const int* in_sizes, int n_in,
                              void* d_out, int out_size) {
    const float* xs    = (const float*)d_in[0];   // [3, N, 64]
    const int*   eidx  = (const int*)  d_in[1];   // [2, E]
    const int*   eattr = (const int*)  d_in[2];   // [E], 1..3
    const float* Wa    = (const float*)d_in[3];
    const float* ba    = (const float*)d_in[4];
    const float* Wd    = (const float*)d_in[5];
    const float* bd    = (const float*)d_in[6];
    const float* Wb    = (const float*)d_in[7];   // [3,64,64]
    const float* bb    = (const float*)d_in[8];   // [3,64]
    const float* gamma = (const float*)d_in[9];
    const float* beta  = (const float*)d_in[10];
    float* out = (float*)d_out;

    const int* src = eidx;
    const int* dst = eidx + EE;

    // 0) zero accumulated scratch
    k_zero<<<(NN + 255) / 256, 256>>>();

    // 1) five GEMMs
    dim3 ggrid((NN + 63) / 64, 5);
    k_gemm5<<<ggrid, 256>>>(xs, Wa, ba, Wd, bd, Wb, bb);

    // 2) histogram
    k_hist<<<(EE + 255) / 256, 256>>>(dst);

    // 3) multi-block scan
    k_scan_sums<<<SCAN_NB, 512>>>();
    k_scan_tops<<<1, 128>>>();
    k_scan_final<<<SCAN_NB, 512>>>();

    // 4) scatter into destination-sorted order
    k_scatter<<<(EE + 255) / 256, 256>>>(src, dst, eattr);

    // 5) gated aggregation -> x_new into d_out
    k_aggregate<<<NN, 64>>>(out);

    // 6-7) batchnorm (training-mode batch stats) + relu, in place
    k_stats<<<128, 256>>>(out);
    k_norm<<<(NN * DD + 255) / 256, 256>>>(out, gamma, beta);
}